// round 3
// baseline (speedup 1.0000x reference)
#include <cuda_runtime.h>
#include <math.h>

#define NB 8
#define NC 80
#define NTOT 21824
#define NCAND 3320
#define TOPN 1000
#define MAXDET 100
#define MIN_SCOREF 0.05f
#define NMS_THRF 0.6f
#define NEGF -1000000000.0f

// Precise libdevice exp, immune to --use_fast_math macro remapping.
extern "C" __device__ float __nv_expf(float);

// scratch (device globals; no dynamic allocation allowed)
__device__ float  g_score[NB * NTOT];
__device__ int    g_class[NB * NTOT];
__device__ float4 g_box[NB * NTOT];

__device__ float  g_cs[NB * NCAND];
__device__ int    g_cc[NB * NCAND];
__device__ float4 g_cb[NB * NCAND];

__constant__ int LVL_OFF[6]  = {0, 16384, 20480, 21504, 21760, 21824};
__constant__ int CAND_OFF[6] = {0, 1000, 2000, 3000, 3256, 3320};

struct Ptrs {
    const float* cls[5];
    const float* reg[5];
    const float* ctr[5];
};

__device__ __forceinline__ float sigmoid_precise(float x) {
    return __fdiv_rn(1.0f, 1.0f + __nv_expf(-x));
}

// ---------------------------------------------------------------------------
// Kernel 1: per-anchor decode (score, class, box)
// ---------------------------------------------------------------------------
__global__ __launch_bounds__(256) void decode_kernel(Ptrs p) {
    int idx = blockIdx.x * blockDim.x + threadIdx.x;
    if (idx >= NB * NTOT) return;
    int img = idx / NTOT;
    int a   = idx - img * NTOT;

    int l;
    if (a < 16384) l = 0;
    else if (a < 20480) l = 1;
    else if (a < 21504) l = 2;
    else if (a < 21760) l = 3;
    else l = 4;

    int n  = a - LVL_OFF[l];
    int hw = 128 >> l;
    int lb = 7 - l;
    int h  = n >> lb;       // first spatial dim
    int w  = n & (hw - 1);  // second spatial dim
    int cell = (img * hw + h) * hw + w;

    // ---- cls max + argmax (sigmoid is monotonic -> operate on logits) ----
    const float4* cls4 = (const float4*)(p.cls[l] + (size_t)cell * NC);
    float m = -3.4e38f;
    int mi = 0;
#pragma unroll
    for (int j = 0; j < 20; j++) {
        float4 v = cls4[j];
        if (v.x > m) { m = v.x; mi = 4 * j + 0; }
        if (v.y > m) { m = v.y; mi = 4 * j + 1; }
        if (v.z > m) { m = v.z; mi = 4 * j + 2; }
        if (v.w > m) { m = v.w; mi = 4 * j + 3; }
    }

    float csig = sigmoid_precise(m);
    float ctrv = p.ctr[l][cell];
    float tsig = sigmoid_precise(ctrv);
    float score = __fsqrt_rn(csig * tsig);

    // ---- box decode (precise exp; truncation is a knife-edge) ----
    // positions: pos[n] = ((w+0.5)*stride, (h+0.5)*stride)
    float4 r = *(const float4*)(p.reg[l] + (size_t)cell * 4);
    float stride = (float)(8 << l);
    float px = ((float)w + 0.5f) * stride;
    float py = ((float)h + 0.5f) * stride;
    float fx1 = px - __nv_expf(r.x);
    float fy1 = py - __nv_expf(r.y);
    float fx2 = px + __nv_expf(r.z);
    float fy2 = py + __nv_expf(r.w);
    int ix1 = (int)fx1, iy1 = (int)fy1, ix2 = (int)fx2, iy2 = (int)fy2;
    ix1 = max(ix1, 0);
    iy1 = max(iy1, 0);
    ix2 = min(ix2, 1023);
    iy2 = min(iy2, 1023);

    int o = img * NTOT + a;
    g_score[o] = score;
    g_class[o] = mi;
    g_box[o]   = make_float4((float)ix1, (float)iy1, (float)ix2, (float)iy2);
}

// ---------------------------------------------------------------------------
// Kernel 2: exact top-1000 radix select + compaction per (image, level)
//           (levels with N <= 1000: copy all)
// ---------------------------------------------------------------------------
__global__ __launch_bounds__(1024) void select_kernel() {
    int img = blockIdx.x / 5;
    int l   = blockIdx.x % 5;
    int Nl  = LVL_OFF[l + 1] - LVL_OFF[l];
    int tid = threadIdx.x;

    const float*  sc = g_score + img * NTOT + LVL_OFF[l];
    const int*    cl = g_class + img * NTOT + LVL_OFF[l];
    const float4* bx = g_box   + img * NTOT + LVL_OFF[l];
    float*  cs = g_cs + img * NCAND + CAND_OFF[l];
    int*    cc = g_cc + img * NCAND + CAND_OFF[l];
    float4* cb = g_cb + img * NCAND + CAND_OFF[l];

    if (Nl <= TOPN) {
        for (int i = tid; i < Nl; i += blockDim.x) {
            cs[i] = sc[i];
            cc[i] = cl[i];
            cb[i] = bx[i];
        }
        return;
    }

    __shared__ int hist[256];
    __shared__ int ssum[256];
    __shared__ unsigned int sh_prefix;
    __shared__ int sh_k;
    __shared__ int cntG, cntE;

    if (tid == 0) { sh_prefix = 0u; sh_k = TOPN; cntG = 0; cntE = 0; }
    __syncthreads();

    // 4 radix passes, MSB first. Scores are >= 0, so raw float bits are
    // monotonic in value.
    for (int pass = 0; pass < 4; pass++) {
        int shift = 24 - 8 * pass;
        for (int i = tid; i < 256; i += blockDim.x) hist[i] = 0;
        __syncthreads();

        unsigned int prefix = sh_prefix;
        unsigned int maskHi = (pass == 0) ? 0u : (0xFFFFFFFFu << (shift + 8));
        for (int i = tid; i < Nl; i += blockDim.x) {
            unsigned int u = __float_as_uint(sc[i]);
            if ((u & maskHi) == prefix)
                atomicAdd(&hist[(u >> shift) & 255], 1);
        }
        __syncthreads();

        // suffix-sum (count of digits >= d)
        if (tid < 256) ssum[tid] = hist[tid];
        __syncthreads();
        for (int off = 1; off < 256; off <<= 1) {
            int v = 0;
            if (tid < 256)
                v = ssum[tid] + ((tid + off < 256) ? ssum[tid + off] : 0);
            __syncthreads();
            if (tid < 256) ssum[tid] = v;
            __syncthreads();
        }

        // read-before-write barrier discipline for sh_k / sh_prefix
        int k = sh_k;
        int hi = 0;
        bool win = false;
        if (tid < 256) {
            hi = (tid < 255) ? ssum[tid + 1] : 0;
            win = (ssum[tid] >= k) && (hi < k);
        }
        __syncthreads();
        if (win) {
            sh_prefix = prefix | ((unsigned int)tid << shift);
            sh_k = k - hi;
        }
        __syncthreads();
    }

    unsigned int T = sh_prefix;   // exact bits of the 1000th largest score
    int kEq = sh_k;               // how many entries equal to T to keep
    int G   = TOPN - kEq;         // count strictly greater than T

    for (int i = tid; i < Nl; i += blockDim.x) {
        unsigned int u = __float_as_uint(sc[i]);
        int dst = -1;
        if (u > T) {
            dst = atomicAdd(&cntG, 1);
        } else if (u == T) {
            int e = atomicAdd(&cntE, 1);
            if (e < kEq) dst = G + e;
        }
        if (dst >= 0) {
            cs[dst] = sc[i];
            cc[dst] = cl[i];
            cb[dst] = bx[i];
        }
    }
}

// ---------------------------------------------------------------------------
// Kernel 3: sequential greedy NMS (argmax + suppress, MAXDET iterations)
//           One block per image; candidates live in registers.
// ---------------------------------------------------------------------------
#define PER 13  // 13 * 256 = 3328 >= 3320

__global__ __launch_bounds__(256) void nms_kernel(float* out) {
    int img = blockIdx.x;
    int tid = threadIdx.x;

    float s[PER], x1[PER], y1[PER], x2[PER], y2[PER], ar[PER];
    int   kls[PER];

#pragma unroll
    for (int j = 0; j < PER; j++) {
        int idx = j * 256 + tid;
        if (idx < NCAND) {
            float sv = g_cs[img * NCAND + idx];
            s[j] = (sv > MIN_SCOREF) ? sv : NEGF;
            float4 b = g_cb[img * NCAND + idx];
            x1[j] = b.x; y1[j] = b.y; x2[j] = b.z; y2[j] = b.w;
            ar[j] = (b.z - b.x) * (b.w - b.y);
            kls[j] = g_cc[img * NCAND + idx];
        } else {
            s[j] = NEGF;
            x1[j] = y1[j] = x2[j] = y2[j] = ar[j] = 0.0f;
            kls[j] = 0;
        }
    }

    float* oS = out + img * MAXDET;
    float* oC = out + NB * MAXDET + img * MAXDET;
    float* oB = out + 2 * NB * MAXDET + (size_t)img * MAXDET * 4;
    for (int i = tid; i < MAXDET; i += 256) { oS[i] = -1.0f; oC[i] = -1.0f; }
    for (int i = tid; i < MAXDET * 4; i += 256) oB[i] = -1.0f;

    __shared__ unsigned long long warpBest[8];
    __shared__ unsigned long long bestKey;
    __shared__ float bb[5];
    __syncthreads();

    for (int it = 0; it < MAXDET; it++) {
        // local argmax (packed key: score bits high, ~idx low for tie-break)
        unsigned long long best = 0ull;
#pragma unroll
        for (int j = 0; j < PER; j++) {
            if (s[j] > MIN_SCOREF) {
                unsigned long long key =
                    ((unsigned long long)__float_as_uint(s[j]) << 32) |
                    (unsigned int)(0xFFFFFFFFu - (unsigned int)(j * 256 + tid));
                best = (key > best) ? key : best;
            }
        }
#pragma unroll
        for (int off = 16; off; off >>= 1) {
            unsigned long long o = __shfl_down_sync(0xFFFFFFFFu, best, off);
            best = (o > best) ? o : best;
        }
        if ((tid & 31) == 0) warpBest[tid >> 5] = best;
        __syncthreads();
        if (tid == 0) {
            unsigned long long bk = warpBest[0];
#pragma unroll
            for (int wp = 1; wp < 8; wp++)
                bk = (warpBest[wp] > bk) ? warpBest[wp] : bk;
            bestKey = bk;
        }
        __syncthreads();

        unsigned long long bk = bestKey;
        if (bk == 0ull) break;  // uniform: nothing above MIN_SCORE remains

        int bi = (int)(0xFFFFFFFFu - (unsigned int)(bk & 0xFFFFFFFFu));
        if (tid == (bi & 255)) {
            int j = bi >> 8;
            bb[0] = x1[j]; bb[1] = y1[j]; bb[2] = x2[j]; bb[3] = y2[j];
            bb[4] = ar[j];
            oS[it] = s[j];
            oC[it] = (float)kls[j];
            oB[it * 4 + 0] = x1[j];
            oB[it * 4 + 1] = y1[j];
            oB[it * 4 + 2] = x2[j];
            oB[it * 4 + 3] = y2[j];
            s[j] = NEGF;
        }
        __syncthreads();

        float bx1 = bb[0], by1 = bb[1], bx2 = bb[2], by2 = bb[3], ba = bb[4];
#pragma unroll
        for (int j = 0; j < PER; j++) {
            if (s[j] > MIN_SCOREF) {
                float iw = fminf(x2[j], bx2) - fmaxf(x1[j], bx1);
                float ih = fminf(y2[j], by2) - fmaxf(y1[j], by1);
                iw = fmaxf(iw, 0.0f);
                ih = fmaxf(ih, 0.0f);
                float inter = iw * ih;
                // precise IEEE division: IoU-vs-0.6 is a knife-edge
                float iou = __fdiv_rn(inter, ar[j] + ba - inter + 1e-12f);
                if (iou > NMS_THRF) s[j] = NEGF;
            }
        }
        __syncthreads();
    }
}

// ---------------------------------------------------------------------------
extern "C" void kernel_launch(void* const* d_in, const int* in_sizes, int n_in,
                              void* d_out, int out_size) {
    (void)out_size;
    Ptrs p;

    // Expected element counts per level
    long long clsSz[5], regSz[5], ctrSz[5];
    for (int i = 0; i < 5; i++) {
        long long hw = 128 >> i;
        clsSz[i] = (long long)NB * hw * hw * NC;
        regSz[i] = (long long)NB * hw * hw * 4;
        ctrSz[i] = (long long)NB * hw * hw;
    }

    // Detect input ordering at runtime.
    // Layout A (interleaved, dict insertion order): cls0,reg0,ctr0,cls1,...
    // Layout B (blocked, signature order): cls0..cls4, reg0..reg4, ctr0..ctr4
    bool interleaved = true, blocked = true;
    if (n_in == 15) {
        for (int i = 0; i < 5; i++) {
            if ((long long)in_sizes[3 * i]     != clsSz[i] ||
                (long long)in_sizes[3 * i + 1] != regSz[i] ||
                (long long)in_sizes[3 * i + 2] != ctrSz[i])
                interleaved = false;
            if ((long long)in_sizes[i]      != clsSz[i] ||
                (long long)in_sizes[5 + i]  != regSz[i] ||
                (long long)in_sizes[10 + i] != ctrSz[i])
                blocked = false;
        }
    }

    if (interleaved) {
        for (int i = 0; i < 5; i++) {
            p.cls[i] = (const float*)d_in[3 * i];
            p.reg[i] = (const float*)d_in[3 * i + 1];
            p.ctr[i] = (const float*)d_in[3 * i + 2];
        }
    } else {
        // blocked (or fall back to signature order)
        for (int i = 0; i < 5; i++) {
            p.cls[i] = (const float*)d_in[i];
            p.reg[i] = (const float*)d_in[5 + i];
            p.ctr[i] = (const float*)d_in[10 + i];
        }
    }

    float* out = (float*)d_out;

    int total = NB * NTOT;
    decode_kernel<<<(total + 255) / 256, 256>>>(p);
    select_kernel<<<NB * 5, 1024>>>();
    nms_kernel<<<NB, 256>>>(out);
}

// round 4
// speedup vs baseline: 2.6963x; 2.6963x over previous
#include <cuda_runtime.h>
#include <math.h>

#define NB 8
#define NC 80
#define NTOT 21824
#define NCAND 3320
#define NSORT 4096
#define TOPN 1000
#define MAXDET 100
#define MIN_SCOREF 0.05f
#define NMS_THRF 0.6f
#define NEGF -1000000000.0f

// Precise libdevice exp, immune to --use_fast_math macro remapping.
extern "C" __device__ float __nv_expf(float);

// scratch (device globals; no dynamic allocation allowed)
__device__ float  g_score[NB * NTOT];
__device__ int    g_class[NB * NTOT];
__device__ float4 g_box[NB * NTOT];

__device__ float  g_cs[NB * NCAND];
__device__ int    g_cc[NB * NCAND];
__device__ float4 g_cb[NB * NCAND];

__constant__ int LVL_OFF[6]  = {0, 16384, 20480, 21504, 21760, 21824};
__constant__ int CAND_OFF[6] = {0, 1000, 2000, 3000, 3256, 3320};

struct Ptrs {
    const float* cls[5];
    const float* reg[5];
    const float* ctr[5];
};

__device__ __forceinline__ float sigmoid_precise(float x) {
    return __fdiv_rn(1.0f, 1.0f + __nv_expf(-x));
}

// ---------------------------------------------------------------------------
// Kernel 1: per-anchor decode. TWO threads per anchor (40 classes each) to
// double memory-level parallelism (round-3 grid was occupancy-capped at 57%).
// ---------------------------------------------------------------------------
__global__ __launch_bounds__(256) void decode_kernel(Ptrs p) {
    int gt = blockIdx.x * blockDim.x + threadIdx.x;
    if (gt >= NB * NTOT * 2) return;
    int half = gt & 1;
    int pair = gt >> 1;
    int img  = pair / NTOT;
    int a    = pair - img * NTOT;

    int l;
    if (a < 16384) l = 0;
    else if (a < 20480) l = 1;
    else if (a < 21504) l = 2;
    else if (a < 21760) l = 3;
    else l = 4;

    int n  = a - LVL_OFF[l];
    int hw = 128 >> l;
    int lb = 7 - l;
    int h  = n >> lb;
    int w  = n & (hw - 1);
    int cell = (img * hw + h) * hw + w;

    // ---- cls max + argmax over this thread's 40 classes ----
    const float4* cls4 = (const float4*)(p.cls[l] + (size_t)cell * NC + half * 40);
    float m = -3.4e38f;
    int mi = half * 40;
#pragma unroll
    for (int j = 0; j < 10; j++) {
        float4 v = cls4[j];
        int base = half * 40 + 4 * j;
        if (v.x > m) { m = v.x; mi = base + 0; }
        if (v.y > m) { m = v.y; mi = base + 1; }
        if (v.z > m) { m = v.z; mi = base + 2; }
        if (v.w > m) { m = v.w; mi = base + 3; }
    }
    // combine halves (lanes 2p, 2p+1); on exact tie keep lower class index
    float mo  = __shfl_xor_sync(0xFFFFFFFFu, m, 1);
    int   mio = __shfl_xor_sync(0xFFFFFFFFu, mi, 1);
    if (mo > m || (mo == m && mio < mi)) { m = mo; mi = mio; }
    if (half) return;

    float csig = sigmoid_precise(m);
    float ctrv = p.ctr[l][cell];
    float tsig = sigmoid_precise(ctrv);
    float score = __fsqrt_rn(csig * tsig);

    // ---- box decode (precise exp; int truncation is a knife-edge) ----
    float4 r = *(const float4*)(p.reg[l] + (size_t)cell * 4);
    float stride = (float)(8 << l);
    float px = ((float)w + 0.5f) * stride;
    float py = ((float)h + 0.5f) * stride;
    int ix1 = (int)(px - __nv_expf(r.x));
    int iy1 = (int)(py - __nv_expf(r.y));
    int ix2 = (int)(px + __nv_expf(r.z));
    int iy2 = (int)(py + __nv_expf(r.w));
    ix1 = max(ix1, 0);
    iy1 = max(iy1, 0);
    ix2 = min(ix2, 1023);
    iy2 = min(iy2, 1023);

    int o = img * NTOT + a;
    g_score[o] = score;
    g_class[o] = mi;
    g_box[o]   = make_float4((float)ix1, (float)iy1, (float)ix2, (float)iy2);
}

// ---------------------------------------------------------------------------
// Kernel 2: exact top-1000 radix select + compaction per (image, level).
// Suffix-scan of the 256-bin histogram done by a single warp (no barrier loop).
// ---------------------------------------------------------------------------
__global__ __launch_bounds__(1024) void select_kernel() {
    int img = blockIdx.x / 5;
    int l   = blockIdx.x % 5;
    int Nl  = LVL_OFF[l + 1] - LVL_OFF[l];
    int tid = threadIdx.x;

    const float*  sc = g_score + img * NTOT + LVL_OFF[l];
    const int*    cl = g_class + img * NTOT + LVL_OFF[l];
    const float4* bx = g_box   + img * NTOT + LVL_OFF[l];
    float*  cs = g_cs + img * NCAND + CAND_OFF[l];
    int*    cc = g_cc + img * NCAND + CAND_OFF[l];
    float4* cb = g_cb + img * NCAND + CAND_OFF[l];

    if (Nl <= TOPN) {
        for (int i = tid; i < Nl; i += blockDim.x) {
            cs[i] = sc[i];
            cc[i] = cl[i];
            cb[i] = bx[i];
        }
        return;
    }

    __shared__ int hist[256];
    __shared__ unsigned int sh_prefix;
    __shared__ int sh_k;
    __shared__ int cntG, cntE;

    if (tid == 0) { sh_prefix = 0u; sh_k = TOPN; cntG = 0; cntE = 0; }
    __syncthreads();

    // 4 radix passes, MSB first. Scores >= 0 -> raw bits monotonic in value.
    for (int pass = 0; pass < 4; pass++) {
        int shift = 24 - 8 * pass;
        if (tid < 256) hist[tid] = 0;
        __syncthreads();

        unsigned int prefix = sh_prefix;
        unsigned int maskHi = (pass == 0) ? 0u : (0xFFFFFFFFu << (shift + 8));
        for (int i = tid; i < Nl; i += blockDim.x) {
            unsigned int u = __float_as_uint(sc[i]);
            if ((u & maskHi) == prefix)
                atomicAdd(&hist[(u >> shift) & 255], 1);
        }
        __syncthreads();

        if (tid < 32) {
            int v[8];
#pragma unroll
            for (int q = 0; q < 8; q++) v[q] = hist[tid * 8 + q];
            int tot = 0;
#pragma unroll
            for (int q = 0; q < 8; q++) tot += v[q];
            // inclusive suffix over lanes (sum of lanes >= tid)
            int suf = tot;
#pragma unroll
            for (int off = 16; off; off >>= 1) {
                int o = __shfl_down_sync(0xFFFFFFFFu, suf, off);
                if (tid + off < 32) suf += o;
            }
            int above = suf - tot;   // sum of bins in lanes > tid
            int k = sh_k;
            __syncwarp();            // everyone reads sh_k before winner writes
            int sarr[9];
            sarr[8] = above;
#pragma unroll
            for (int q = 7; q >= 0; q--) sarr[q] = sarr[q + 1] + v[q];
#pragma unroll
            for (int q = 0; q < 8; q++) {
                if (sarr[q] >= k && sarr[q + 1] < k) {
                    sh_prefix = prefix | ((unsigned int)(tid * 8 + q) << shift);
                    sh_k = k - sarr[q + 1];
                }
            }
        }
        __syncthreads();
    }

    unsigned int T = sh_prefix;   // exact bits of the 1000th largest score
    int kEq = sh_k;               // how many entries equal to T to keep
    int G   = TOPN - kEq;         // count strictly greater than T

    for (int i = tid; i < Nl; i += blockDim.x) {
        unsigned int u = __float_as_uint(sc[i]);
        int dst = -1;
        if (u > T) {
            dst = atomicAdd(&cntG, 1);
        } else if (u == T) {
            int e = atomicAdd(&cntE, 1);
            if (e < kEq) dst = G + e;
        }
        if (dst >= 0) {
            cs[dst] = sc[i];
            cc[dst] = cl[i];
            cb[dst] = bx[i];
        }
    }
}

// ---------------------------------------------------------------------------
// Kernel 3: sorted-greedy NMS.
//   (a) bitonic sort 4096 u64 keys (score_bits<<32 | idx), descending
//   (b) gather payloads into smem in sorted order
//   (c) warp 0 scans in order; a candidate is kept iff no previously-KEPT box
//       has IoU > thr (exactly equivalent to repeated argmax+suppress).
//       Early-exit at 100 kept or when scores drop to <= MIN_SCORE.
// ---------------------------------------------------------------------------
#define SMEM_KEYS_B   (NSORT * 8)            // 32768
#define SMEM_ARR_B    (NCAND * 4)            // 13280
#define SMEM_NMS_B    (SMEM_KEYS_B + 7 * SMEM_ARR_B)   // keys + 6 float + 1 int

__global__ __launch_bounds__(1024) void nms_kernel(float* out) {
    extern __shared__ char smem_raw[];
    unsigned long long* key = (unsigned long long*)smem_raw;
    float* sx1 = (float*)(smem_raw + SMEM_KEYS_B);
    float* sy1 = sx1 + NCAND;
    float* sx2 = sy1 + NCAND;
    float* sy2 = sx2 + NCAND;
    float* sar = sy2 + NCAND;
    float* ssc = sar + NCAND;
    int*   scl = (int*)(ssc + NCAND);

    __shared__ float kx1[MAXDET], ky1[MAXDET], kx2[MAXDET], ky2[MAXDET], kar[MAXDET];

    int img = blockIdx.x;
    int tid = threadIdx.x;

    // init outputs to -1
    float* oS = out + img * MAXDET;
    float* oC = out + NB * MAXDET + img * MAXDET;
    float* oB = out + 2 * NB * MAXDET + (size_t)img * MAXDET * 4;
    for (int i = tid; i < MAXDET; i += 1024) { oS[i] = -1.0f; oC[i] = -1.0f; }
    for (int i = tid; i < MAXDET * 4; i += 1024) oB[i] = -1.0f;

    // build keys
    for (int i = tid; i < NSORT; i += 1024) {
        if (i < NCAND) {
            unsigned int sb = __float_as_uint(g_cs[img * NCAND + i]);
            key[i] = ((unsigned long long)sb << 32) | (unsigned int)i;
        } else {
            key[i] = 0ull;
        }
    }
    __syncthreads();

    // bitonic sort, descending
    for (int k = 2; k <= NSORT; k <<= 1) {
        for (int j = k >> 1; j > 0; j >>= 1) {
            for (int t = tid; t < NSORT / 2; t += 1024) {
                int i   = 2 * t - (t & (j - 1));
                int ixj = i + j;
                bool desc = ((i & k) == 0);
                unsigned long long a = key[i];
                unsigned long long b = key[ixj];
                if ((a < b) == desc) { key[i] = b; key[ixj] = a; }
            }
            __syncthreads();
        }
    }

    // gather payloads in sorted order
    for (int i = tid; i < NCAND; i += 1024) {
        unsigned long long kv = key[i];
        int idx = (int)(unsigned int)kv;
        ssc[i] = __uint_as_float((unsigned int)(kv >> 32));
        float4 b = g_cb[img * NCAND + idx];
        sx1[i] = b.x; sy1[i] = b.y; sx2[i] = b.z; sy2[i] = b.w;
        sar[i] = (b.z - b.x) * (b.w - b.y);
        scl[i] = g_cc[img * NCAND + idx];
    }
    __syncthreads();

    // warp-0 sorted-greedy scan
    if (tid < 32) {
        int lane = tid;
        int kk = 0;
        for (int i = 0; i < NCAND; i++) {
            float sc = ssc[i];
            if (!(sc > MIN_SCOREF)) break;   // sorted: nothing better follows
            float bx1 = sx1[i], by1 = sy1[i], bx2 = sx2[i], by2 = sy2[i];
            float ba = sar[i];
            bool sup = false;
            for (int b = lane; b < kk; b += 32) {
                float iw = fminf(kx2[b], bx2) - fmaxf(kx1[b], bx1);
                float ih = fminf(ky2[b], by2) - fmaxf(ky1[b], by1);
                iw = fmaxf(iw, 0.0f);
                ih = fmaxf(ih, 0.0f);
                float inter = iw * ih;
                float iou = __fdiv_rn(inter, kar[b] + ba - inter + 1e-12f);
                if (iou > NMS_THRF) sup = true;
            }
            if (__any_sync(0xFFFFFFFFu, sup)) continue;
            if (lane == 0) {
                kx1[kk] = bx1; ky1[kk] = by1; kx2[kk] = bx2; ky2[kk] = by2;
                kar[kk] = ba;
                oS[kk] = sc;
                oC[kk] = (float)scl[i];
                oB[kk * 4 + 0] = bx1;
                oB[kk * 4 + 1] = by1;
                oB[kk * 4 + 2] = bx2;
                oB[kk * 4 + 3] = by2;
            }
            __syncwarp();
            kk++;
            if (kk == MAXDET) break;
        }
    }
}

// ---------------------------------------------------------------------------
extern "C" void kernel_launch(void* const* d_in, const int* in_sizes, int n_in,
                              void* d_out, int out_size) {
    (void)out_size;
    Ptrs p;

    long long clsSz[5], regSz[5], ctrSz[5];
    for (int i = 0; i < 5; i++) {
        long long hw = 128 >> i;
        clsSz[i] = (long long)NB * hw * hw * NC;
        regSz[i] = (long long)NB * hw * hw * 4;
        ctrSz[i] = (long long)NB * hw * hw;
    }

    bool interleaved = true;
    if (n_in == 15) {
        for (int i = 0; i < 5; i++) {
            if ((long long)in_sizes[3 * i]     != clsSz[i] ||
                (long long)in_sizes[3 * i + 1] != regSz[i] ||
                (long long)in_sizes[3 * i + 2] != ctrSz[i])
                interleaved = false;
        }
    } else {
        interleaved = false;
    }

    if (interleaved) {
        for (int i = 0; i < 5; i++) {
            p.cls[i] = (const float*)d_in[3 * i];
            p.reg[i] = (const float*)d_in[3 * i + 1];
            p.ctr[i] = (const float*)d_in[3 * i + 2];
        }
    } else {
        for (int i = 0; i < 5; i++) {
            p.cls[i] = (const float*)d_in[i];
            p.reg[i] = (const float*)d_in[5 + i];
            p.ctr[i] = (const float*)d_in[10 + i];
        }
    }

    float* out = (float*)d_out;

    static bool attr_done = false;
    if (!attr_done) {
        cudaFuncSetAttribute(nms_kernel,
                             cudaFuncAttributeMaxDynamicSharedMemorySize,
                             SMEM_NMS_B);
        attr_done = true;
    }

    int total2 = NB * NTOT * 2;
    decode_kernel<<<(total2 + 255) / 256, 256>>>(p);
    select_kernel<<<NB * 5, 1024>>>();
    nms_kernel<<<NB, 1024, SMEM_NMS_B>>>(out);
}

// round 5
// speedup vs baseline: 2.6969x; 1.0002x over previous
#include <cuda_runtime.h>
#include <math.h>

#define NB 8
#define NC 80
#define NTOT 21824
#define NCAND 3320
#define NSORT 4096
#define TOPN 1000
#define MAXDET 100
#define MIN_SCOREF 0.05f
#define NMS_THRF 0.6f
#define NEGF -1000000000.0f

// Precise libdevice exp, immune to --use_fast_math macro remapping.
extern "C" __device__ float __nv_expf(float);

// scratch (device globals; no dynamic allocation allowed)
__device__ float  g_score[NB * NTOT];
__device__ int    g_class[NB * NTOT];
__device__ float4 g_box[NB * NTOT];

__device__ float  g_cs[NB * NCAND];
__device__ int    g_cc[NB * NCAND];
__device__ float4 g_cb[NB * NCAND];

__constant__ int LVL_OFF[6]  = {0, 16384, 20480, 21504, 21760, 21824};
__constant__ int CAND_OFF[6] = {0, 1000, 2000, 3000, 3256, 3320};

struct Ptrs {
    const float* cls[5];
    const float* reg[5];
    const float* ctr[5];
};

__device__ __forceinline__ float sigmoid_precise(float x) {
    return __fdiv_rn(1.0f, 1.0f + __nv_expf(-x));
}

// ---------------------------------------------------------------------------
// Kernel 1: per-anchor decode. TWO threads per anchor (40 classes each) to
// double memory-level parallelism (round-3 grid was occupancy-capped at 57%).
// ---------------------------------------------------------------------------
__global__ __launch_bounds__(256) void decode_kernel(Ptrs p) {
    int gt = blockIdx.x * blockDim.x + threadIdx.x;
    if (gt >= NB * NTOT * 2) return;
    int half = gt & 1;
    int pair = gt >> 1;
    int img  = pair / NTOT;
    int a    = pair - img * NTOT;

    int l;
    if (a < 16384) l = 0;
    else if (a < 20480) l = 1;
    else if (a < 21504) l = 2;
    else if (a < 21760) l = 3;
    else l = 4;

    int n  = a - LVL_OFF[l];
    int hw = 128 >> l;
    int lb = 7 - l;
    int h  = n >> lb;
    int w  = n & (hw - 1);
    int cell = (img * hw + h) * hw + w;

    // ---- cls max + argmax over this thread's 40 classes ----
    const float4* cls4 = (const float4*)(p.cls[l] + (size_t)cell * NC + half * 40);
    float m = -3.4e38f;
    int mi = half * 40;
#pragma unroll
    for (int j = 0; j < 10; j++) {
        float4 v = cls4[j];
        int base = half * 40 + 4 * j;
        if (v.x > m) { m = v.x; mi = base + 0; }
        if (v.y > m) { m = v.y; mi = base + 1; }
        if (v.z > m) { m = v.z; mi = base + 2; }
        if (v.w > m) { m = v.w; mi = base + 3; }
    }
    // combine halves (lanes 2p, 2p+1); on exact tie keep lower class index
    float mo  = __shfl_xor_sync(0xFFFFFFFFu, m, 1);
    int   mio = __shfl_xor_sync(0xFFFFFFFFu, mi, 1);
    if (mo > m || (mo == m && mio < mi)) { m = mo; mi = mio; }
    if (half) return;

    float csig = sigmoid_precise(m);
    float ctrv = p.ctr[l][cell];
    float tsig = sigmoid_precise(ctrv);
    float score = __fsqrt_rn(csig * tsig);

    // ---- box decode (precise exp; int truncation is a knife-edge) ----
    float4 r = *(const float4*)(p.reg[l] + (size_t)cell * 4);
    float stride = (float)(8 << l);
    float px = ((float)w + 0.5f) * stride;
    float py = ((float)h + 0.5f) * stride;
    int ix1 = (int)(px - __nv_expf(r.x));
    int iy1 = (int)(py - __nv_expf(r.y));
    int ix2 = (int)(px + __nv_expf(r.z));
    int iy2 = (int)(py + __nv_expf(r.w));
    ix1 = max(ix1, 0);
    iy1 = max(iy1, 0);
    ix2 = min(ix2, 1023);
    iy2 = min(iy2, 1023);

    int o = img * NTOT + a;
    g_score[o] = score;
    g_class[o] = mi;
    g_box[o]   = make_float4((float)ix1, (float)iy1, (float)ix2, (float)iy2);
}

// ---------------------------------------------------------------------------
// Kernel 2: exact top-1000 radix select + compaction per (image, level).
// Suffix-scan of the 256-bin histogram done by a single warp (no barrier loop).
// ---------------------------------------------------------------------------
__global__ __launch_bounds__(1024) void select_kernel() {
    int img = blockIdx.x / 5;
    int l   = blockIdx.x % 5;
    int Nl  = LVL_OFF[l + 1] - LVL_OFF[l];
    int tid = threadIdx.x;

    const float*  sc = g_score + img * NTOT + LVL_OFF[l];
    const int*    cl = g_class + img * NTOT + LVL_OFF[l];
    const float4* bx = g_box   + img * NTOT + LVL_OFF[l];
    float*  cs = g_cs + img * NCAND + CAND_OFF[l];
    int*    cc = g_cc + img * NCAND + CAND_OFF[l];
    float4* cb = g_cb + img * NCAND + CAND_OFF[l];

    if (Nl <= TOPN) {
        for (int i = tid; i < Nl; i += blockDim.x) {
            cs[i] = sc[i];
            cc[i] = cl[i];
            cb[i] = bx[i];
        }
        return;
    }

    __shared__ int hist[256];
    __shared__ unsigned int sh_prefix;
    __shared__ int sh_k;
    __shared__ int cntG, cntE;

    if (tid == 0) { sh_prefix = 0u; sh_k = TOPN; cntG = 0; cntE = 0; }
    __syncthreads();

    // 4 radix passes, MSB first. Scores >= 0 -> raw bits monotonic in value.
    for (int pass = 0; pass < 4; pass++) {
        int shift = 24 - 8 * pass;
        if (tid < 256) hist[tid] = 0;
        __syncthreads();

        unsigned int prefix = sh_prefix;
        unsigned int maskHi = (pass == 0) ? 0u : (0xFFFFFFFFu << (shift + 8));
        for (int i = tid; i < Nl; i += blockDim.x) {
            unsigned int u = __float_as_uint(sc[i]);
            if ((u & maskHi) == prefix)
                atomicAdd(&hist[(u >> shift) & 255], 1);
        }
        __syncthreads();

        if (tid < 32) {
            int v[8];
#pragma unroll
            for (int q = 0; q < 8; q++) v[q] = hist[tid * 8 + q];
            int tot = 0;
#pragma unroll
            for (int q = 0; q < 8; q++) tot += v[q];
            // inclusive suffix over lanes (sum of lanes >= tid)
            int suf = tot;
#pragma unroll
            for (int off = 16; off; off >>= 1) {
                int o = __shfl_down_sync(0xFFFFFFFFu, suf, off);
                if (tid + off < 32) suf += o;
            }
            int above = suf - tot;   // sum of bins in lanes > tid
            int k = sh_k;
            __syncwarp();            // everyone reads sh_k before winner writes
            int sarr[9];
            sarr[8] = above;
#pragma unroll
            for (int q = 7; q >= 0; q--) sarr[q] = sarr[q + 1] + v[q];
#pragma unroll
            for (int q = 0; q < 8; q++) {
                if (sarr[q] >= k && sarr[q + 1] < k) {
                    sh_prefix = prefix | ((unsigned int)(tid * 8 + q) << shift);
                    sh_k = k - sarr[q + 1];
                }
            }
        }
        __syncthreads();
    }

    unsigned int T = sh_prefix;   // exact bits of the 1000th largest score
    int kEq = sh_k;               // how many entries equal to T to keep
    int G   = TOPN - kEq;         // count strictly greater than T

    for (int i = tid; i < Nl; i += blockDim.x) {
        unsigned int u = __float_as_uint(sc[i]);
        int dst = -1;
        if (u > T) {
            dst = atomicAdd(&cntG, 1);
        } else if (u == T) {
            int e = atomicAdd(&cntE, 1);
            if (e < kEq) dst = G + e;
        }
        if (dst >= 0) {
            cs[dst] = sc[i];
            cc[dst] = cl[i];
            cb[dst] = bx[i];
        }
    }
}

// ---------------------------------------------------------------------------
// Kernel 3: sorted-greedy NMS.
//   (a) bitonic sort 4096 u64 keys (score_bits<<32 | idx), descending
//   (b) gather payloads into smem in sorted order
//   (c) warp 0 scans in order; a candidate is kept iff no previously-KEPT box
//       has IoU > thr (exactly equivalent to repeated argmax+suppress).
//       Early-exit at 100 kept or when scores drop to <= MIN_SCORE.
// ---------------------------------------------------------------------------
#define SMEM_KEYS_B   (NSORT * 8)            // 32768
#define SMEM_ARR_B    (NCAND * 4)            // 13280
#define SMEM_NMS_B    (SMEM_KEYS_B + 7 * SMEM_ARR_B)   // keys + 6 float + 1 int

__global__ __launch_bounds__(1024) void nms_kernel(float* out) {
    extern __shared__ char smem_raw[];
    unsigned long long* key = (unsigned long long*)smem_raw;
    float* sx1 = (float*)(smem_raw + SMEM_KEYS_B);
    float* sy1 = sx1 + NCAND;
    float* sx2 = sy1 + NCAND;
    float* sy2 = sx2 + NCAND;
    float* sar = sy2 + NCAND;
    float* ssc = sar + NCAND;
    int*   scl = (int*)(ssc + NCAND);

    __shared__ float kx1[MAXDET], ky1[MAXDET], kx2[MAXDET], ky2[MAXDET], kar[MAXDET];

    int img = blockIdx.x;
    int tid = threadIdx.x;

    // init outputs to -1
    float* oS = out + img * MAXDET;
    float* oC = out + NB * MAXDET + img * MAXDET;
    float* oB = out + 2 * NB * MAXDET + (size_t)img * MAXDET * 4;
    for (int i = tid; i < MAXDET; i += 1024) { oS[i] = -1.0f; oC[i] = -1.0f; }
    for (int i = tid; i < MAXDET * 4; i += 1024) oB[i] = -1.0f;

    // build keys
    for (int i = tid; i < NSORT; i += 1024) {
        if (i < NCAND) {
            unsigned int sb = __float_as_uint(g_cs[img * NCAND + i]);
            key[i] = ((unsigned long long)sb << 32) | (unsigned int)i;
        } else {
            key[i] = 0ull;
        }
    }
    __syncthreads();

    // bitonic sort, descending
    for (int k = 2; k <= NSORT; k <<= 1) {
        for (int j = k >> 1; j > 0; j >>= 1) {
            for (int t = tid; t < NSORT / 2; t += 1024) {
                int i   = 2 * t - (t & (j - 1));
                int ixj = i + j;
                bool desc = ((i & k) == 0);
                unsigned long long a = key[i];
                unsigned long long b = key[ixj];
                if ((a < b) == desc) { key[i] = b; key[ixj] = a; }
            }
            __syncthreads();
        }
    }

    // gather payloads in sorted order
    for (int i = tid; i < NCAND; i += 1024) {
        unsigned long long kv = key[i];
        int idx = (int)(unsigned int)kv;
        ssc[i] = __uint_as_float((unsigned int)(kv >> 32));
        float4 b = g_cb[img * NCAND + idx];
        sx1[i] = b.x; sy1[i] = b.y; sx2[i] = b.z; sy2[i] = b.w;
        sar[i] = (b.z - b.x) * (b.w - b.y);
        scl[i] = g_cc[img * NCAND + idx];
    }
    __syncthreads();

    // warp-0 sorted-greedy scan
    if (tid < 32) {
        int lane = tid;
        int kk = 0;
        for (int i = 0; i < NCAND; i++) {
            float sc = ssc[i];
            if (!(sc > MIN_SCOREF)) break;   // sorted: nothing better follows
            float bx1 = sx1[i], by1 = sy1[i], bx2 = sx2[i], by2 = sy2[i];
            float ba = sar[i];
            bool sup = false;
            for (int b = lane; b < kk; b += 32) {
                float iw = fminf(kx2[b], bx2) - fmaxf(kx1[b], bx1);
                float ih = fminf(ky2[b], by2) - fmaxf(ky1[b], by1);
                iw = fmaxf(iw, 0.0f);
                ih = fmaxf(ih, 0.0f);
                float inter = iw * ih;
                float iou = __fdiv_rn(inter, kar[b] + ba - inter + 1e-12f);
                if (iou > NMS_THRF) sup = true;
            }
            if (__any_sync(0xFFFFFFFFu, sup)) continue;
            if (lane == 0) {
                kx1[kk] = bx1; ky1[kk] = by1; kx2[kk] = bx2; ky2[kk] = by2;
                kar[kk] = ba;
                oS[kk] = sc;
                oC[kk] = (float)scl[i];
                oB[kk * 4 + 0] = bx1;
                oB[kk * 4 + 1] = by1;
                oB[kk * 4 + 2] = bx2;
                oB[kk * 4 + 3] = by2;
            }
            __syncwarp();
            kk++;
            if (kk == MAXDET) break;
        }
    }
}

// ---------------------------------------------------------------------------
extern "C" void kernel_launch(void* const* d_in, const int* in_sizes, int n_in,
                              void* d_out, int out_size) {
    (void)out_size;
    Ptrs p;

    long long clsSz[5], regSz[5], ctrSz[5];
    for (int i = 0; i < 5; i++) {
        long long hw = 128 >> i;
        clsSz[i] = (long long)NB * hw * hw * NC;
        regSz[i] = (long long)NB * hw * hw * 4;
        ctrSz[i] = (long long)NB * hw * hw;
    }

    bool interleaved = true;
    if (n_in == 15) {
        for (int i = 0; i < 5; i++) {
            if ((long long)in_sizes[3 * i]     != clsSz[i] ||
                (long long)in_sizes[3 * i + 1] != regSz[i] ||
                (long long)in_sizes[3 * i + 2] != ctrSz[i])
                interleaved = false;
        }
    } else {
        interleaved = false;
    }

    if (interleaved) {
        for (int i = 0; i < 5; i++) {
            p.cls[i] = (const float*)d_in[3 * i];
            p.reg[i] = (const float*)d_in[3 * i + 1];
            p.ctr[i] = (const float*)d_in[3 * i + 2];
        }
    } else {
        for (int i = 0; i < 5; i++) {
            p.cls[i] = (const float*)d_in[i];
            p.reg[i] = (const float*)d_in[5 + i];
            p.ctr[i] = (const float*)d_in[10 + i];
        }
    }

    float* out = (float*)d_out;

    static bool attr_done = false;
    if (!attr_done) {
        cudaFuncSetAttribute(nms_kernel,
                             cudaFuncAttributeMaxDynamicSharedMemorySize,
                             SMEM_NMS_B);
        attr_done = true;
    }

    int total2 = NB * NTOT * 2;
    decode_kernel<<<(total2 + 255) / 256, 256>>>(p);
    select_kernel<<<NB * 5, 1024>>>();
    nms_kernel<<<NB, 1024, SMEM_NMS_B>>>(out);
}

// round 6
// speedup vs baseline: 2.6975x; 1.0002x over previous
#include <cuda_runtime.h>
#include <math.h>

#define NB 8
#define NC 80
#define NTOT 21824
#define NCAND 3320
#define NSORT 4096
#define TOPN 1000
#define MAXDET 100
#define MIN_SCOREF 0.05f
#define NMS_THRF 0.6f
#define NEGF -1000000000.0f

// Precise libdevice exp, immune to --use_fast_math macro remapping.
extern "C" __device__ float __nv_expf(float);

// scratch (device globals; no dynamic allocation allowed)
__device__ float  g_score[NB * NTOT];
__device__ int    g_class[NB * NTOT];
__device__ float4 g_box[NB * NTOT];

__device__ float  g_cs[NB * NCAND];
__device__ int    g_cc[NB * NCAND];
__device__ float4 g_cb[NB * NCAND];

__constant__ int LVL_OFF[6]  = {0, 16384, 20480, 21504, 21760, 21824};
__constant__ int CAND_OFF[6] = {0, 1000, 2000, 3000, 3256, 3320};

struct Ptrs {
    const float* cls[5];
    const float* reg[5];
    const float* ctr[5];
};

__device__ __forceinline__ float sigmoid_precise(float x) {
    return __fdiv_rn(1.0f, 1.0f + __nv_expf(-x));
}

// ---------------------------------------------------------------------------
// Kernel 1: per-anchor decode. TWO threads per anchor (40 classes each) to
// double memory-level parallelism (round-3 grid was occupancy-capped at 57%).
// ---------------------------------------------------------------------------
__global__ __launch_bounds__(256) void decode_kernel(Ptrs p) {
    int gt = blockIdx.x * blockDim.x + threadIdx.x;
    if (gt >= NB * NTOT * 2) return;
    int half = gt & 1;
    int pair = gt >> 1;
    int img  = pair / NTOT;
    int a    = pair - img * NTOT;

    int l;
    if (a < 16384) l = 0;
    else if (a < 20480) l = 1;
    else if (a < 21504) l = 2;
    else if (a < 21760) l = 3;
    else l = 4;

    int n  = a - LVL_OFF[l];
    int hw = 128 >> l;
    int lb = 7 - l;
    int h  = n >> lb;
    int w  = n & (hw - 1);
    int cell = (img * hw + h) * hw + w;

    // ---- cls max + argmax over this thread's 40 classes ----
    const float4* cls4 = (const float4*)(p.cls[l] + (size_t)cell * NC + half * 40);
    float m = -3.4e38f;
    int mi = half * 40;
#pragma unroll
    for (int j = 0; j < 10; j++) {
        float4 v = cls4[j];
        int base = half * 40 + 4 * j;
        if (v.x > m) { m = v.x; mi = base + 0; }
        if (v.y > m) { m = v.y; mi = base + 1; }
        if (v.z > m) { m = v.z; mi = base + 2; }
        if (v.w > m) { m = v.w; mi = base + 3; }
    }
    // combine halves (lanes 2p, 2p+1); on exact tie keep lower class index
    float mo  = __shfl_xor_sync(0xFFFFFFFFu, m, 1);
    int   mio = __shfl_xor_sync(0xFFFFFFFFu, mi, 1);
    if (mo > m || (mo == m && mio < mi)) { m = mo; mi = mio; }
    if (half) return;

    float csig = sigmoid_precise(m);
    float ctrv = p.ctr[l][cell];
    float tsig = sigmoid_precise(ctrv);
    float score = __fsqrt_rn(csig * tsig);

    // ---- box decode (precise exp; int truncation is a knife-edge) ----
    float4 r = *(const float4*)(p.reg[l] + (size_t)cell * 4);
    float stride = (float)(8 << l);
    float px = ((float)w + 0.5f) * stride;
    float py = ((float)h + 0.5f) * stride;
    int ix1 = (int)(px - __nv_expf(r.x));
    int iy1 = (int)(py - __nv_expf(r.y));
    int ix2 = (int)(px + __nv_expf(r.z));
    int iy2 = (int)(py + __nv_expf(r.w));
    ix1 = max(ix1, 0);
    iy1 = max(iy1, 0);
    ix2 = min(ix2, 1023);
    iy2 = min(iy2, 1023);

    int o = img * NTOT + a;
    g_score[o] = score;
    g_class[o] = mi;
    g_box[o]   = make_float4((float)ix1, (float)iy1, (float)ix2, (float)iy2);
}

// ---------------------------------------------------------------------------
// Kernel 2: exact top-1000 radix select + compaction per (image, level).
// Suffix-scan of the 256-bin histogram done by a single warp (no barrier loop).
// ---------------------------------------------------------------------------
__global__ __launch_bounds__(1024) void select_kernel() {
    int img = blockIdx.x / 5;
    int l   = blockIdx.x % 5;
    int Nl  = LVL_OFF[l + 1] - LVL_OFF[l];
    int tid = threadIdx.x;

    const float*  sc = g_score + img * NTOT + LVL_OFF[l];
    const int*    cl = g_class + img * NTOT + LVL_OFF[l];
    const float4* bx = g_box   + img * NTOT + LVL_OFF[l];
    float*  cs = g_cs + img * NCAND + CAND_OFF[l];
    int*    cc = g_cc + img * NCAND + CAND_OFF[l];
    float4* cb = g_cb + img * NCAND + CAND_OFF[l];

    if (Nl <= TOPN) {
        for (int i = tid; i < Nl; i += blockDim.x) {
            cs[i] = sc[i];
            cc[i] = cl[i];
            cb[i] = bx[i];
        }
        return;
    }

    __shared__ int hist[256];
    __shared__ unsigned int sh_prefix;
    __shared__ int sh_k;
    __shared__ int cntG, cntE;

    if (tid == 0) { sh_prefix = 0u; sh_k = TOPN; cntG = 0; cntE = 0; }
    __syncthreads();

    // 4 radix passes, MSB first. Scores >= 0 -> raw bits monotonic in value.
    for (int pass = 0; pass < 4; pass++) {
        int shift = 24 - 8 * pass;
        if (tid < 256) hist[tid] = 0;
        __syncthreads();

        unsigned int prefix = sh_prefix;
        unsigned int maskHi = (pass == 0) ? 0u : (0xFFFFFFFFu << (shift + 8));
        for (int i = tid; i < Nl; i += blockDim.x) {
            unsigned int u = __float_as_uint(sc[i]);
            if ((u & maskHi) == prefix)
                atomicAdd(&hist[(u >> shift) & 255], 1);
        }
        __syncthreads();

        if (tid < 32) {
            int v[8];
#pragma unroll
            for (int q = 0; q < 8; q++) v[q] = hist[tid * 8 + q];
            int tot = 0;
#pragma unroll
            for (int q = 0; q < 8; q++) tot += v[q];
            // inclusive suffix over lanes (sum of lanes >= tid)
            int suf = tot;
#pragma unroll
            for (int off = 16; off; off >>= 1) {
                int o = __shfl_down_sync(0xFFFFFFFFu, suf, off);
                if (tid + off < 32) suf += o;
            }
            int above = suf - tot;   // sum of bins in lanes > tid
            int k = sh_k;
            __syncwarp();            // everyone reads sh_k before winner writes
            int sarr[9];
            sarr[8] = above;
#pragma unroll
            for (int q = 7; q >= 0; q--) sarr[q] = sarr[q + 1] + v[q];
#pragma unroll
            for (int q = 0; q < 8; q++) {
                if (sarr[q] >= k && sarr[q + 1] < k) {
                    sh_prefix = prefix | ((unsigned int)(tid * 8 + q) << shift);
                    sh_k = k - sarr[q + 1];
                }
            }
        }
        __syncthreads();
    }

    unsigned int T = sh_prefix;   // exact bits of the 1000th largest score
    int kEq = sh_k;               // how many entries equal to T to keep
    int G   = TOPN - kEq;         // count strictly greater than T

    for (int i = tid; i < Nl; i += blockDim.x) {
        unsigned int u = __float_as_uint(sc[i]);
        int dst = -1;
        if (u > T) {
            dst = atomicAdd(&cntG, 1);
        } else if (u == T) {
            int e = atomicAdd(&cntE, 1);
            if (e < kEq) dst = G + e;
        }
        if (dst >= 0) {
            cs[dst] = sc[i];
            cc[dst] = cl[i];
            cb[dst] = bx[i];
        }
    }
}

// ---------------------------------------------------------------------------
// Kernel 3: sorted-greedy NMS.
//   (a) bitonic sort 4096 u64 keys (score_bits<<32 | idx), descending
//   (b) gather payloads into smem in sorted order
//   (c) warp 0 scans in order; a candidate is kept iff no previously-KEPT box
//       has IoU > thr (exactly equivalent to repeated argmax+suppress).
//       Early-exit at 100 kept or when scores drop to <= MIN_SCORE.
// ---------------------------------------------------------------------------
#define SMEM_KEYS_B   (NSORT * 8)            // 32768
#define SMEM_ARR_B    (NCAND * 4)            // 13280
#define SMEM_NMS_B    (SMEM_KEYS_B + 7 * SMEM_ARR_B)   // keys + 6 float + 1 int

__global__ __launch_bounds__(1024) void nms_kernel(float* out) {
    extern __shared__ char smem_raw[];
    unsigned long long* key = (unsigned long long*)smem_raw;
    float* sx1 = (float*)(smem_raw + SMEM_KEYS_B);
    float* sy1 = sx1 + NCAND;
    float* sx2 = sy1 + NCAND;
    float* sy2 = sx2 + NCAND;
    float* sar = sy2 + NCAND;
    float* ssc = sar + NCAND;
    int*   scl = (int*)(ssc + NCAND);

    __shared__ float kx1[MAXDET], ky1[MAXDET], kx2[MAXDET], ky2[MAXDET], kar[MAXDET];

    int img = blockIdx.x;
    int tid = threadIdx.x;

    // init outputs to -1
    float* oS = out + img * MAXDET;
    float* oC = out + NB * MAXDET + img * MAXDET;
    float* oB = out + 2 * NB * MAXDET + (size_t)img * MAXDET * 4;
    for (int i = tid; i < MAXDET; i += 1024) { oS[i] = -1.0f; oC[i] = -1.0f; }
    for (int i = tid; i < MAXDET * 4; i += 1024) oB[i] = -1.0f;

    // build keys
    for (int i = tid; i < NSORT; i += 1024) {
        if (i < NCAND) {
            unsigned int sb = __float_as_uint(g_cs[img * NCAND + i]);
            key[i] = ((unsigned long long)sb << 32) | (unsigned int)i;
        } else {
            key[i] = 0ull;
        }
    }
    __syncthreads();

    // bitonic sort, descending
    for (int k = 2; k <= NSORT; k <<= 1) {
        for (int j = k >> 1; j > 0; j >>= 1) {
            for (int t = tid; t < NSORT / 2; t += 1024) {
                int i   = 2 * t - (t & (j - 1));
                int ixj = i + j;
                bool desc = ((i & k) == 0);
                unsigned long long a = key[i];
                unsigned long long b = key[ixj];
                if ((a < b) == desc) { key[i] = b; key[ixj] = a; }
            }
            __syncthreads();
        }
    }

    // gather payloads in sorted order
    for (int i = tid; i < NCAND; i += 1024) {
        unsigned long long kv = key[i];
        int idx = (int)(unsigned int)kv;
        ssc[i] = __uint_as_float((unsigned int)(kv >> 32));
        float4 b = g_cb[img * NCAND + idx];
        sx1[i] = b.x; sy1[i] = b.y; sx2[i] = b.z; sy2[i] = b.w;
        sar[i] = (b.z - b.x) * (b.w - b.y);
        scl[i] = g_cc[img * NCAND + idx];
    }
    __syncthreads();

    // warp-0 sorted-greedy scan
    if (tid < 32) {
        int lane = tid;
        int kk = 0;
        for (int i = 0; i < NCAND; i++) {
            float sc = ssc[i];
            if (!(sc > MIN_SCOREF)) break;   // sorted: nothing better follows
            float bx1 = sx1[i], by1 = sy1[i], bx2 = sx2[i], by2 = sy2[i];
            float ba = sar[i];
            bool sup = false;
            for (int b = lane; b < kk; b += 32) {
                float iw = fminf(kx2[b], bx2) - fmaxf(kx1[b], bx1);
                float ih = fminf(ky2[b], by2) - fmaxf(ky1[b], by1);
                iw = fmaxf(iw, 0.0f);
                ih = fmaxf(ih, 0.0f);
                float inter = iw * ih;
                float iou = __fdiv_rn(inter, kar[b] + ba - inter + 1e-12f);
                if (iou > NMS_THRF) sup = true;
            }
            if (__any_sync(0xFFFFFFFFu, sup)) continue;
            if (lane == 0) {
                kx1[kk] = bx1; ky1[kk] = by1; kx2[kk] = bx2; ky2[kk] = by2;
                kar[kk] = ba;
                oS[kk] = sc;
                oC[kk] = (float)scl[i];
                oB[kk * 4 + 0] = bx1;
                oB[kk * 4 + 1] = by1;
                oB[kk * 4 + 2] = bx2;
                oB[kk * 4 + 3] = by2;
            }
            __syncwarp();
            kk++;
            if (kk == MAXDET) break;
        }
    }
}

// ---------------------------------------------------------------------------
extern "C" void kernel_launch(void* const* d_in, const int* in_sizes, int n_in,
                              void* d_out, int out_size) {
    (void)out_size;
    Ptrs p;

    long long clsSz[5], regSz[5], ctrSz[5];
    for (int i = 0; i < 5; i++) {
        long long hw = 128 >> i;
        clsSz[i] = (long long)NB * hw * hw * NC;
        regSz[i] = (long long)NB * hw * hw * 4;
        ctrSz[i] = (long long)NB * hw * hw;
    }

    bool interleaved = true;
    if (n_in == 15) {
        for (int i = 0; i < 5; i++) {
            if ((long long)in_sizes[3 * i]     != clsSz[i] ||
                (long long)in_sizes[3 * i + 1] != regSz[i] ||
                (long long)in_sizes[3 * i + 2] != ctrSz[i])
                interleaved = false;
        }
    } else {
        interleaved = false;
    }

    if (interleaved) {
        for (int i = 0; i < 5; i++) {
            p.cls[i] = (const float*)d_in[3 * i];
            p.reg[i] = (const float*)d_in[3 * i + 1];
            p.ctr[i] = (const float*)d_in[3 * i + 2];
        }
    } else {
        for (int i = 0; i < 5; i++) {
            p.cls[i] = (const float*)d_in[i];
            p.reg[i] = (const float*)d_in[5 + i];
            p.ctr[i] = (const float*)d_in[10 + i];
        }
    }

    float* out = (float*)d_out;

    static bool attr_done = false;
    if (!attr_done) {
        cudaFuncSetAttribute(nms_kernel,
                             cudaFuncAttributeMaxDynamicSharedMemorySize,
                             SMEM_NMS_B);
        attr_done = true;
    }

    int total2 = NB * NTOT * 2;
    decode_kernel<<<(total2 + 255) / 256, 256>>>(p);
    select_kernel<<<NB * 5, 1024>>>();
    nms_kernel<<<NB, 1024, SMEM_NMS_B>>>(out);
}

// round 7
// speedup vs baseline: 2.7025x; 1.0018x over previous
#include <cuda_runtime.h>
#include <math.h>

#define NB 8
#define NC 80
#define NTOT 21824
#define NCAND 3320
#define NSORT 4096
#define TOPN 1000
#define MAXDET 100
#define MIN_SCOREF 0.05f
#define NMS_THRF 0.6f
#define NEGF -1000000000.0f

// Precise libdevice exp, immune to --use_fast_math macro remapping.
extern "C" __device__ float __nv_expf(float);

// scratch (device globals; no dynamic allocation allowed)
__device__ float  g_score[NB * NTOT];
__device__ int    g_class[NB * NTOT];
__device__ float4 g_box[NB * NTOT];

__device__ float  g_cs[NB * NCAND];
__device__ int    g_cc[NB * NCAND];
__device__ float4 g_cb[NB * NCAND];

__constant__ int LVL_OFF[6]  = {0, 16384, 20480, 21504, 21760, 21824};
__constant__ int CAND_OFF[6] = {0, 1000, 2000, 3000, 3256, 3320};

struct Ptrs {
    const float* cls[5];
    const float* reg[5];
    const float* ctr[5];
};

__device__ __forceinline__ float sigmoid_precise(float x) {
    return __fdiv_rn(1.0f, 1.0f + __nv_expf(-x));
}

// ---------------------------------------------------------------------------
// Kernel 1: per-anchor decode. TWO threads per anchor (40 classes each) to
// double memory-level parallelism (round-3 grid was occupancy-capped at 57%).
// ---------------------------------------------------------------------------
__global__ __launch_bounds__(256) void decode_kernel(Ptrs p) {
    int gt = blockIdx.x * blockDim.x + threadIdx.x;
    if (gt >= NB * NTOT * 2) return;
    int half = gt & 1;
    int pair = gt >> 1;
    int img  = pair / NTOT;
    int a    = pair - img * NTOT;

    int l;
    if (a < 16384) l = 0;
    else if (a < 20480) l = 1;
    else if (a < 21504) l = 2;
    else if (a < 21760) l = 3;
    else l = 4;

    int n  = a - LVL_OFF[l];
    int hw = 128 >> l;
    int lb = 7 - l;
    int h  = n >> lb;
    int w  = n & (hw - 1);
    int cell = (img * hw + h) * hw + w;

    // ---- cls max + argmax over this thread's 40 classes ----
    const float4* cls4 = (const float4*)(p.cls[l] + (size_t)cell * NC + half * 40);
    float m = -3.4e38f;
    int mi = half * 40;
#pragma unroll
    for (int j = 0; j < 10; j++) {
        float4 v = cls4[j];
        int base = half * 40 + 4 * j;
        if (v.x > m) { m = v.x; mi = base + 0; }
        if (v.y > m) { m = v.y; mi = base + 1; }
        if (v.z > m) { m = v.z; mi = base + 2; }
        if (v.w > m) { m = v.w; mi = base + 3; }
    }
    // combine halves (lanes 2p, 2p+1); on exact tie keep lower class index
    float mo  = __shfl_xor_sync(0xFFFFFFFFu, m, 1);
    int   mio = __shfl_xor_sync(0xFFFFFFFFu, mi, 1);
    if (mo > m || (mo == m && mio < mi)) { m = mo; mi = mio; }
    if (half) return;

    float csig = sigmoid_precise(m);
    float ctrv = p.ctr[l][cell];
    float tsig = sigmoid_precise(ctrv);
    float score = __fsqrt_rn(csig * tsig);

    // ---- box decode (precise exp; int truncation is a knife-edge) ----
    float4 r = *(const float4*)(p.reg[l] + (size_t)cell * 4);
    float stride = (float)(8 << l);
    float px = ((float)w + 0.5f) * stride;
    float py = ((float)h + 0.5f) * stride;
    int ix1 = (int)(px - __nv_expf(r.x));
    int iy1 = (int)(py - __nv_expf(r.y));
    int ix2 = (int)(px + __nv_expf(r.z));
    int iy2 = (int)(py + __nv_expf(r.w));
    ix1 = max(ix1, 0);
    iy1 = max(iy1, 0);
    ix2 = min(ix2, 1023);
    iy2 = min(iy2, 1023);

    int o = img * NTOT + a;
    g_score[o] = score;
    g_class[o] = mi;
    g_box[o]   = make_float4((float)ix1, (float)iy1, (float)ix2, (float)iy2);
}

// ---------------------------------------------------------------------------
// Kernel 2: exact top-1000 radix select + compaction per (image, level).
// Suffix-scan of the 256-bin histogram done by a single warp (no barrier loop).
// ---------------------------------------------------------------------------
__global__ __launch_bounds__(1024) void select_kernel() {
    int img = blockIdx.x / 5;
    int l   = blockIdx.x % 5;
    int Nl  = LVL_OFF[l + 1] - LVL_OFF[l];
    int tid = threadIdx.x;

    const float*  sc = g_score + img * NTOT + LVL_OFF[l];
    const int*    cl = g_class + img * NTOT + LVL_OFF[l];
    const float4* bx = g_box   + img * NTOT + LVL_OFF[l];
    float*  cs = g_cs + img * NCAND + CAND_OFF[l];
    int*    cc = g_cc + img * NCAND + CAND_OFF[l];
    float4* cb = g_cb + img * NCAND + CAND_OFF[l];

    if (Nl <= TOPN) {
        for (int i = tid; i < Nl; i += blockDim.x) {
            cs[i] = sc[i];
            cc[i] = cl[i];
            cb[i] = bx[i];
        }
        return;
    }

    __shared__ int hist[256];
    __shared__ unsigned int sh_prefix;
    __shared__ int sh_k;
    __shared__ int cntG, cntE;

    if (tid == 0) { sh_prefix = 0u; sh_k = TOPN; cntG = 0; cntE = 0; }
    __syncthreads();

    // 4 radix passes, MSB first. Scores >= 0 -> raw bits monotonic in value.
    for (int pass = 0; pass < 4; pass++) {
        int shift = 24 - 8 * pass;
        if (tid < 256) hist[tid] = 0;
        __syncthreads();

        unsigned int prefix = sh_prefix;
        unsigned int maskHi = (pass == 0) ? 0u : (0xFFFFFFFFu << (shift + 8));
        for (int i = tid; i < Nl; i += blockDim.x) {
            unsigned int u = __float_as_uint(sc[i]);
            if ((u & maskHi) == prefix)
                atomicAdd(&hist[(u >> shift) & 255], 1);
        }
        __syncthreads();

        if (tid < 32) {
            int v[8];
#pragma unroll
            for (int q = 0; q < 8; q++) v[q] = hist[tid * 8 + q];
            int tot = 0;
#pragma unroll
            for (int q = 0; q < 8; q++) tot += v[q];
            // inclusive suffix over lanes (sum of lanes >= tid)
            int suf = tot;
#pragma unroll
            for (int off = 16; off; off >>= 1) {
                int o = __shfl_down_sync(0xFFFFFFFFu, suf, off);
                if (tid + off < 32) suf += o;
            }
            int above = suf - tot;   // sum of bins in lanes > tid
            int k = sh_k;
            __syncwarp();            // everyone reads sh_k before winner writes
            int sarr[9];
            sarr[8] = above;
#pragma unroll
            for (int q = 7; q >= 0; q--) sarr[q] = sarr[q + 1] + v[q];
#pragma unroll
            for (int q = 0; q < 8; q++) {
                if (sarr[q] >= k && sarr[q + 1] < k) {
                    sh_prefix = prefix | ((unsigned int)(tid * 8 + q) << shift);
                    sh_k = k - sarr[q + 1];
                }
            }
        }
        __syncthreads();
    }

    unsigned int T = sh_prefix;   // exact bits of the 1000th largest score
    int kEq = sh_k;               // how many entries equal to T to keep
    int G   = TOPN - kEq;         // count strictly greater than T

    for (int i = tid; i < Nl; i += blockDim.x) {
        unsigned int u = __float_as_uint(sc[i]);
        int dst = -1;
        if (u > T) {
            dst = atomicAdd(&cntG, 1);
        } else if (u == T) {
            int e = atomicAdd(&cntE, 1);
            if (e < kEq) dst = G + e;
        }
        if (dst >= 0) {
            cs[dst] = sc[i];
            cc[dst] = cl[i];
            cb[dst] = bx[i];
        }
    }
}

// ---------------------------------------------------------------------------
// Kernel 3: sorted-greedy NMS.
//   (a) bitonic sort 4096 u64 keys (score_bits<<32 | idx), descending
//   (b) gather payloads into smem in sorted order
//   (c) warp 0 scans in order; a candidate is kept iff no previously-KEPT box
//       has IoU > thr (exactly equivalent to repeated argmax+suppress).
//       Early-exit at 100 kept or when scores drop to <= MIN_SCORE.
// ---------------------------------------------------------------------------
#define SMEM_KEYS_B   (NSORT * 8)            // 32768
#define SMEM_ARR_B    (NCAND * 4)            // 13280
#define SMEM_NMS_B    (SMEM_KEYS_B + 7 * SMEM_ARR_B)   // keys + 6 float + 1 int

__global__ __launch_bounds__(1024) void nms_kernel(float* out) {
    extern __shared__ char smem_raw[];
    unsigned long long* key = (unsigned long long*)smem_raw;
    float* sx1 = (float*)(smem_raw + SMEM_KEYS_B);
    float* sy1 = sx1 + NCAND;
    float* sx2 = sy1 + NCAND;
    float* sy2 = sx2 + NCAND;
    float* sar = sy2 + NCAND;
    float* ssc = sar + NCAND;
    int*   scl = (int*)(ssc + NCAND);

    __shared__ float kx1[MAXDET], ky1[MAXDET], kx2[MAXDET], ky2[MAXDET], kar[MAXDET];

    int img = blockIdx.x;
    int tid = threadIdx.x;

    // init outputs to -1
    float* oS = out + img * MAXDET;
    float* oC = out + NB * MAXDET + img * MAXDET;
    float* oB = out + 2 * NB * MAXDET + (size_t)img * MAXDET * 4;
    for (int i = tid; i < MAXDET; i += 1024) { oS[i] = -1.0f; oC[i] = -1.0f; }
    for (int i = tid; i < MAXDET * 4; i += 1024) oB[i] = -1.0f;

    // build keys
    for (int i = tid; i < NSORT; i += 1024) {
        if (i < NCAND) {
            unsigned int sb = __float_as_uint(g_cs[img * NCAND + i]);
            key[i] = ((unsigned long long)sb << 32) | (unsigned int)i;
        } else {
            key[i] = 0ull;
        }
    }
    __syncthreads();

    // bitonic sort, descending
    for (int k = 2; k <= NSORT; k <<= 1) {
        for (int j = k >> 1; j > 0; j >>= 1) {
            for (int t = tid; t < NSORT / 2; t += 1024) {
                int i   = 2 * t - (t & (j - 1));
                int ixj = i + j;
                bool desc = ((i & k) == 0);
                unsigned long long a = key[i];
                unsigned long long b = key[ixj];
                if ((a < b) == desc) { key[i] = b; key[ixj] = a; }
            }
            __syncthreads();
        }
    }

    // gather payloads in sorted order
    for (int i = tid; i < NCAND; i += 1024) {
        unsigned long long kv = key[i];
        int idx = (int)(unsigned int)kv;
        ssc[i] = __uint_as_float((unsigned int)(kv >> 32));
        float4 b = g_cb[img * NCAND + idx];
        sx1[i] = b.x; sy1[i] = b.y; sx2[i] = b.z; sy2[i] = b.w;
        sar[i] = (b.z - b.x) * (b.w - b.y);
        scl[i] = g_cc[img * NCAND + idx];
    }
    __syncthreads();

    // warp-0 sorted-greedy scan
    if (tid < 32) {
        int lane = tid;
        int kk = 0;
        for (int i = 0; i < NCAND; i++) {
            float sc = ssc[i];
            if (!(sc > MIN_SCOREF)) break;   // sorted: nothing better follows
            float bx1 = sx1[i], by1 = sy1[i], bx2 = sx2[i], by2 = sy2[i];
            float ba = sar[i];
            bool sup = false;
            for (int b = lane; b < kk; b += 32) {
                float iw = fminf(kx2[b], bx2) - fmaxf(kx1[b], bx1);
                float ih = fminf(ky2[b], by2) - fmaxf(ky1[b], by1);
                iw = fmaxf(iw, 0.0f);
                ih = fmaxf(ih, 0.0f);
                float inter = iw * ih;
                float iou = __fdiv_rn(inter, kar[b] + ba - inter + 1e-12f);
                if (iou > NMS_THRF) sup = true;
            }
            if (__any_sync(0xFFFFFFFFu, sup)) continue;
            if (lane == 0) {
                kx1[kk] = bx1; ky1[kk] = by1; kx2[kk] = bx2; ky2[kk] = by2;
                kar[kk] = ba;
                oS[kk] = sc;
                oC[kk] = (float)scl[i];
                oB[kk * 4 + 0] = bx1;
                oB[kk * 4 + 1] = by1;
                oB[kk * 4 + 2] = bx2;
                oB[kk * 4 + 3] = by2;
            }
            __syncwarp();
            kk++;
            if (kk == MAXDET) break;
        }
    }
}

// ---------------------------------------------------------------------------
extern "C" void kernel_launch(void* const* d_in, const int* in_sizes, int n_in,
                              void* d_out, int out_size) {
    (void)out_size;
    Ptrs p;

    long long clsSz[5], regSz[5], ctrSz[5];
    for (int i = 0; i < 5; i++) {
        long long hw = 128 >> i;
        clsSz[i] = (long long)NB * hw * hw * NC;
        regSz[i] = (long long)NB * hw * hw * 4;
        ctrSz[i] = (long long)NB * hw * hw;
    }

    bool interleaved = true;
    if (n_in == 15) {
        for (int i = 0; i < 5; i++) {
            if ((long long)in_sizes[3 * i]     != clsSz[i] ||
                (long long)in_sizes[3 * i + 1] != regSz[i] ||
                (long long)in_sizes[3 * i + 2] != ctrSz[i])
                interleaved = false;
        }
    } else {
        interleaved = false;
    }

    if (interleaved) {
        for (int i = 0; i < 5; i++) {
            p.cls[i] = (const float*)d_in[3 * i];
            p.reg[i] = (const float*)d_in[3 * i + 1];
            p.ctr[i] = (const float*)d_in[3 * i + 2];
        }
    } else {
        for (int i = 0; i < 5; i++) {
            p.cls[i] = (const float*)d_in[i];
            p.reg[i] = (const float*)d_in[5 + i];
            p.ctr[i] = (const float*)d_in[10 + i];
        }
    }

    float* out = (float*)d_out;

    static bool attr_done = false;
    if (!attr_done) {
        cudaFuncSetAttribute(nms_kernel,
                             cudaFuncAttributeMaxDynamicSharedMemorySize,
                             SMEM_NMS_B);
        attr_done = true;
    }

    int total2 = NB * NTOT * 2;
    decode_kernel<<<(total2 + 255) / 256, 256>>>(p);
    select_kernel<<<NB * 5, 1024>>>();
    nms_kernel<<<NB, 1024, SMEM_NMS_B>>>(out);
}